// round 1
// baseline (speedup 1.0000x reference)
#include <cuda_runtime.h>
#include <cuda_bf16.h>
#include <cstdint>

// Problem sizes (fixed per reference)
#define NB_B 64          // batch
#define NN   4096        // nodes
#define DD   16          // feature dim
#define CC   (NB_B*DD)   // 1024 fused columns (b*16+d)

// GEMM tiling
#define BM 128
#define BN 128
#define BK 16
#define KT (NN/BK)       // 256 k-tiles

// Scratch (allocation-guard-safe): H = lrelu(x@W) in [n, b*16+d] layout, O = layer output
__device__ float g_H[(size_t)NN * CC];
__device__ float g_O[(size_t)NN * CC];

// ---------------- packed f32x2 helpers (Blackwell FFMA2 path) ----------------
__device__ __forceinline__ unsigned long long splat2(float a) {
    unsigned long long r;
    asm("mov.b64 %0, {%1, %1};" : "=l"(r) : "f"(a));
    return r;
}
__device__ __forceinline__ void fma2(unsigned long long& d, unsigned long long a,
                                     unsigned long long b) {
    asm("fma.rn.f32x2 %0, %1, %2, %0;" : "+l"(d) : "l"(a), "l"(b));
}
__device__ __forceinline__ void unpack2(unsigned long long v, float& lo, float& hi) {
    asm("mov.b64 {%0, %1}, %2;" : "=f"(lo), "=f"(hi) : "l"(v));
}

// ---------------- kernel 1: h = leaky_relu(x @ W), write [n, b*16+d] ----------------
// mode 0: X is original input, layout (b, n, d)
// mode 1: X is previous layer output, layout (n, b*16+d)
__global__ void lin_lrelu_kernel(const float* __restrict__ X,
                                 const float* __restrict__ W,
                                 float* __restrict__ H, int mode) {
    __shared__ float sW[DD][DD];
    int t = threadIdx.x;                 // blockDim = 256 exactly
    sW[t >> 4][t & 15] = W[t];
    __syncthreads();

    int idx = blockIdx.x * 256 + t;      // one thread per (m, b)
    int m = idx >> 6;                    // / 64
    int b = idx & 63;

    const float* xp = mode ? (X + (size_t)m * CC + (size_t)b * DD)
                           : (X + ((size_t)b * NN + m) * DD);
    float xv[16];
#pragma unroll
    for (int j = 0; j < 4; j++) {
        float4 v = reinterpret_cast<const float4*>(xp)[j];
        xv[4 * j + 0] = v.x; xv[4 * j + 1] = v.y;
        xv[4 * j + 2] = v.z; xv[4 * j + 3] = v.w;
    }
    float h[16];
#pragma unroll
    for (int e = 0; e < 16; e++) h[e] = 0.0f;
#pragma unroll
    for (int d = 0; d < 16; d++) {
        float xd = xv[d];
#pragma unroll
        for (int e = 0; e < 16; e++) h[e] = fmaf(xd, sW[d][e], h[e]);
    }
    float* hp = H + (size_t)m * CC + (size_t)b * DD;
#pragma unroll
    for (int j = 0; j < 4; j++) {
        float a0 = h[4 * j + 0], a1 = h[4 * j + 1], a2 = h[4 * j + 2], a3 = h[4 * j + 3];
        float4 v;
        v.x = a0 > 0.0f ? a0 : 0.2f * a0;
        v.y = a1 > 0.0f ? a1 : 0.2f * a1;
        v.z = a2 > 0.0f ? a2 : 0.2f * a2;
        v.w = a3 > 0.0f ? a3 : 0.2f * a3;
        reinterpret_cast<float4*>(hp)[j] = v;
    }
}

// ---------------- kernel 2: C[n,c] = sum_m adj[n,m]*H[m,c] + H[n,c] ----------------
// final_layer: write to Dout in (b, n, d) layout; else write g_O in [n, c] layout.
__global__ __launch_bounds__(256, 2)
void gemm_gcn_kernel(const float* __restrict__ A,    // adj [4096,4096]
                     const float* __restrict__ Bm,   // H   [4096,1024]
                     float* __restrict__ Cout,       // g_O (non-final)
                     float* __restrict__ Dout,       // d_out (final)
                     int final_layer) {
    __shared__ float As[2][BK][BM + 4];   // transposed A tile, padded
    __shared__ float Bs[2][BK][BN];

    int tid = threadIdx.x;
    int tx = tid & 15, ty = tid >> 4;
    int bx = blockIdx.x, by = blockIdx.y;

    const float* Ap = A + (size_t)by * BM * NN;
    const float* Bp = Bm + (size_t)bx * BN;

    unsigned long long acc[8][4];
#pragma unroll
    for (int i = 0; i < 8; i++)
#pragma unroll
        for (int j = 0; j < 4; j++) acc[i][j] = 0ull;

    // ---- prologue: load tile 0 directly into smem buffer 0 ----
#pragma unroll
    for (int p = 0; p < 2; p++) {
        int idx = tid + p * 256;
        int r = idx >> 2, q = idx & 3;
        float4 v = *reinterpret_cast<const float4*>(Ap + (size_t)r * NN + q * 4);
        As[0][q * 4 + 0][r] = v.x; As[0][q * 4 + 1][r] = v.y;
        As[0][q * 4 + 2][r] = v.z; As[0][q * 4 + 3][r] = v.w;
    }
#pragma unroll
    for (int p = 0; p < 2; p++) {
        int idx = tid + p * 256;
        int r = idx >> 5, c4 = idx & 31;
        float4 v = *reinterpret_cast<const float4*>(Bp + (size_t)r * CC + c4 * 4);
        *reinterpret_cast<float4*>(&Bs[0][r][c4 * 4]) = v;
    }
    __syncthreads();

    const int arow = ty * 8, bcol = tx * 8;

    for (int kt = 0; kt < KT; kt++) {
        int cur = kt & 1;
        float4 ra[2], rb[2];
        bool more = (kt + 1 < KT);
        if (more) {
            int kb = (kt + 1) * BK;
#pragma unroll
            for (int p = 0; p < 2; p++) {
                int idx = tid + p * 256;
                int r = idx >> 2, q = idx & 3;
                ra[p] = *reinterpret_cast<const float4*>(Ap + (size_t)r * NN + kb + q * 4);
            }
#pragma unroll
            for (int p = 0; p < 2; p++) {
                int idx = tid + p * 256;
                int r = idx >> 5, c4 = idx & 31;
                rb[p] = *reinterpret_cast<const float4*>(Bp + (size_t)(kb + r) * CC + c4 * 4);
            }
        }

#pragma unroll
        for (int k = 0; k < BK; k++) {
            float4 alo = *reinterpret_cast<const float4*>(&As[cur][k][arow]);
            float4 ahi = *reinterpret_cast<const float4*>(&As[cur][k][arow + 4]);
            ulonglong2 bl = *reinterpret_cast<const ulonglong2*>(&Bs[cur][k][bcol]);
            ulonglong2 bh = *reinterpret_cast<const ulonglong2*>(&Bs[cur][k][bcol + 4]);
            unsigned long long b2[4] = {bl.x, bl.y, bh.x, bh.y};
            float av[8] = {alo.x, alo.y, alo.z, alo.w, ahi.x, ahi.y, ahi.z, ahi.w};
#pragma unroll
            for (int i = 0; i < 8; i++) {
                unsigned long long a2 = splat2(av[i]);
#pragma unroll
                for (int j = 0; j < 4; j++) fma2(acc[i][j], a2, b2[j]);
            }
        }

        if (more) {
            int nb = cur ^ 1;
#pragma unroll
            for (int p = 0; p < 2; p++) {
                int idx = tid + p * 256;
                int r = idx >> 2, q = idx & 3;
                As[nb][q * 4 + 0][r] = ra[p].x; As[nb][q * 4 + 1][r] = ra[p].y;
                As[nb][q * 4 + 2][r] = ra[p].z; As[nb][q * 4 + 3][r] = ra[p].w;
            }
#pragma unroll
            for (int p = 0; p < 2; p++) {
                int idx = tid + p * 256;
                int r = idx >> 5, c4 = idx & 31;
                *reinterpret_cast<float4*>(&Bs[nb][r][c4 * 4]) = rb[p];
            }
        }
        __syncthreads();
    }

    // ---- epilogue: add identity (H row n) and store ----
#pragma unroll
    for (int i = 0; i < 8; i++) {
        int n = by * BM + arow + i;
        int c = bx * BN + bcol;                  // 8 consecutive cols, same b-group
        float4 id0 = *reinterpret_cast<const float4*>(Bm + (size_t)n * CC + c);
        float4 id1 = *reinterpret_cast<const float4*>(Bm + (size_t)n * CC + c + 4);
        float o[8];
        unpack2(acc[i][0], o[0], o[1]);
        unpack2(acc[i][1], o[2], o[3]);
        unpack2(acc[i][2], o[4], o[5]);
        unpack2(acc[i][3], o[6], o[7]);
        o[0] += id0.x; o[1] += id0.y; o[2] += id0.z; o[3] += id0.w;
        o[4] += id1.x; o[5] += id1.y; o[6] += id1.z; o[7] += id1.w;
        float4 v0 = make_float4(o[0], o[1], o[2], o[3]);
        float4 v1 = make_float4(o[4], o[5], o[6], o[7]);
        if (final_layer) {
            int b = c >> 4;                      // c..c+7 share the same b (c%16 in {0,8})
            int d = c & 15;
            float* op = Dout + (size_t)b * NN * DD + (size_t)n * DD + d;
            reinterpret_cast<float4*>(op)[0] = v0;
            reinterpret_cast<float4*>(op)[1] = v1;
        } else {
            float* op = Cout + (size_t)n * CC + c;
            reinterpret_cast<float4*>(op)[0] = v0;
            reinterpret_cast<float4*>(op)[1] = v1;
        }
    }
}

// ---------------- launch ----------------
extern "C" void kernel_launch(void* const* d_in, const int* in_sizes, int n_in,
                              void* d_out, int out_size) {
    const float* x   = (const float*)d_in[0];
    const float* adj = (const float*)d_in[1];
    // d_in[2] = Identity (unused: I@h == h exactly)
    const float* W0  = (const float*)d_in[3];
    const float* W1  = (const float*)d_in[4];
    const float* W2  = (const float*)d_in[5];
    float* out = (float*)d_out;

    float *pH = nullptr, *pO = nullptr;
    cudaGetSymbolAddress((void**)&pH, g_H);
    cudaGetSymbolAddress((void**)&pO, g_O);

    dim3 ggrid(CC / BN, NN / BM);                 // (8, 32)
    int lin_blocks = (NN * NB_B) / 256;           // 1024

    // layer 0
    lin_lrelu_kernel<<<lin_blocks, 256>>>(x, W0, pH, 0);
    gemm_gcn_kernel<<<ggrid, 256>>>(adj, pH, pO, nullptr, 0);
    // layer 1
    lin_lrelu_kernel<<<lin_blocks, 256>>>(pO, W1, pH, 1);
    gemm_gcn_kernel<<<ggrid, 256>>>(adj, pH, pO, nullptr, 0);
    // layer 2
    lin_lrelu_kernel<<<lin_blocks, 256>>>(pO, W2, pH, 1);
    gemm_gcn_kernel<<<ggrid, 256>>>(adj, pH, nullptr, out, 1);
}

// round 3
// speedup vs baseline: 6.4788x; 6.4788x over previous
#include <cuda_runtime.h>
#include <cuda_bf16.h>
#include <cstdint>

#define NB_B 64
#define NN   4096
#define DD   16
#define CC   1024

#define BM 128
#define BN 128
#define BKB 64              // K bytes per stage (32 bf16)
#define STAGES 4
#define KTILES 128          // 4096/32
#define TILEB 8192          // one operand tile: 128 rows * 64 B
#define STGB  (2*TILEB)     // 16 KB per stage
#define DSMEM (STAGES*STGB) // 64 KB

// ---- scratch ----
__device__ float          g_H [(size_t)NN*CC];
__device__ float          g_O [(size_t)NN*CC];
__device__ __nv_bfloat16  g_adjb[(size_t)NN*NN];
__device__ __nv_bfloat16  g_HT[(size_t)CC*NN];

__device__ __forceinline__ uint32_t smem_u32(const void* p) {
    uint32_t a;
    asm("{ .reg .u64 t; cvta.to.shared.u64 t, %1; cvt.u32.u64 %0, t; }" : "=r"(a) : "l"(p));
    return a;
}
__device__ __forceinline__ void cp16(uint32_t dst, const void* src) {
    asm volatile("cp.async.cg.shared.global [%0], [%1], 16;" :: "r"(dst), "l"(src) : "memory");
}
// 64B rows, 4x16B chunks; conflict-free for ldmatrix phases
__device__ __forceinline__ uint32_t swzoff(int r, int q) {
    return (uint32_t)((r << 6) + ((q ^ ((r >> 1) & 3)) << 4));
}

#define LDSM4(R, addr) \
    asm volatile("ldmatrix.sync.aligned.m8n8.x4.shared.b16 {%0,%1,%2,%3}, [%4];" \
        : "=r"((R)[0]), "=r"((R)[1]), "=r"((R)[2]), "=r"((R)[3]) : "r"(addr))

#define MMA(C, A_, B0, B1) \
    asm volatile("mma.sync.aligned.m16n8k16.row.col.f32.bf16.bf16.f32 " \
        "{%0,%1,%2,%3}, {%4,%5,%6,%7}, {%8,%9}, {%0,%1,%2,%3};" \
        : "+f"((C)[0]), "+f"((C)[1]), "+f"((C)[2]), "+f"((C)[3]) \
        : "r"((A_)[0]), "r"((A_)[1]), "r"((A_)[2]), "r"((A_)[3]), "r"(B0), "r"(B1))

// ================= adj fp32 -> bf16 =================
__global__ void cvt_adj_kernel(const float* __restrict__ A, __nv_bfloat16* __restrict__ Ab) {
    size_t idx = (size_t)blockIdx.x * 256 + threadIdx.x;
    const float4* src = reinterpret_cast<const float4*>(A) + idx * 2;
    float4 a = src[0], b = src[1];
    union { __nv_bfloat162 h[4]; uint4 u; } pk;
    pk.h[0] = __floats2bfloat162_rn(a.x, a.y);
    pk.h[1] = __floats2bfloat162_rn(a.z, a.w);
    pk.h[2] = __floats2bfloat162_rn(b.x, b.y);
    pk.h[3] = __floats2bfloat162_rn(b.z, b.w);
    reinterpret_cast<uint4*>(Ab)[idx] = pk.u;
}

// ================= h = lrelu(x@W) fp32 [m,c] =================
__global__ void lin_lrelu_kernel(const float* __restrict__ X, const float* __restrict__ W,
                                 float* __restrict__ H, int mode) {
    __shared__ float sW[DD][DD];
    int t = threadIdx.x;
    sW[t >> 4][t & 15] = W[t];
    __syncthreads();
    int idx = blockIdx.x * 256 + t;
    int m = idx >> 6, b = idx & 63;
    const float* xp = mode ? (X + (size_t)m * CC + (size_t)b * DD)
                           : (X + ((size_t)b * NN + m) * DD);
    float xv[16];
#pragma unroll
    for (int j = 0; j < 4; j++) {
        float4 v = reinterpret_cast<const float4*>(xp)[j];
        xv[4*j] = v.x; xv[4*j+1] = v.y; xv[4*j+2] = v.z; xv[4*j+3] = v.w;
    }
    float h[16];
#pragma unroll
    for (int e = 0; e < 16; e++) h[e] = 0.0f;
#pragma unroll
    for (int d = 0; d < 16; d++) {
        float xd = xv[d];
#pragma unroll
        for (int e = 0; e < 16; e++) h[e] = fmaf(xd, sW[d][e], h[e]);
    }
    float* hp = H + (size_t)m * CC + (size_t)b * DD;
#pragma unroll
    for (int j = 0; j < 4; j++) {
        float4 v;
        v.x = h[4*j]   > 0.f ? h[4*j]   : 0.2f*h[4*j];
        v.y = h[4*j+1] > 0.f ? h[4*j+1] : 0.2f*h[4*j+1];
        v.z = h[4*j+2] > 0.f ? h[4*j+2] : 0.2f*h[4*j+2];
        v.w = h[4*j+3] > 0.f ? h[4*j+3] : 0.2f*h[4*j+3];
        reinterpret_cast<float4*>(hp)[j] = v;
    }
}

// ================= H [m,c] fp32 -> H^T [c,m] bf16 =================
__global__ void transpose_kernel(const float* __restrict__ H, __nv_bfloat16* __restrict__ HT) {
    __shared__ float tile[32][33];
    int c0 = blockIdx.x * 32, m0 = blockIdx.y * 32;
    int tx = threadIdx.x, ty = threadIdx.y;
#pragma unroll
    for (int j = 0; j < 4; j++)
        tile[ty + 8*j][tx] = H[(size_t)(m0 + ty + 8*j) * CC + c0 + tx];
    __syncthreads();
#pragma unroll
    for (int j = 0; j < 4; j++)
        HT[(size_t)(c0 + ty + 8*j) * NN + m0 + tx] = __float2bfloat16(tile[tx][ty + 8*j]);
}

// ================= HMMA GEMM: out = adj@H + H =================
__global__ __launch_bounds__(256, 2)
void gemm_mma_kernel(const __nv_bfloat16* __restrict__ Ab,   // [4096,4096] bf16 row-major
                     const __nv_bfloat16* __restrict__ Bt,   // [1024,4096] bf16 (H^T)
                     const float* __restrict__ Hf,           // [4096,1024] fp32
                     float* __restrict__ Cout, float* __restrict__ Dout,
                     int final_layer) {
    extern __shared__ char dsm[];
    const uint32_t sm = smem_u32(dsm);
    const int tid = threadIdx.x, wid = tid >> 5, l = tid & 31;
    const int bx = blockIdx.x, by = blockIdx.y;
    const int wm = wid >> 2, wn = wid & 3;     // 2 x 4 warp grid -> 64 x 32 warp tile

    const char* gA = (const char*)(Ab + (size_t)by * BM * NN);
    const char* gB = (const char*)(Bt + (size_t)bx * BN * NN);

    // producer offsets: each thread copies 2 A segs + 2 B segs of 16B
    const int r0 = tid >> 2, q0 = tid & 3;
    const uint32_t offL0 = swzoff(r0, q0);
    const uint32_t offL1 = swzoff(r0 + 64, q0);
    const size_t gOff0 = (size_t)r0 * 8192 + q0 * 16;
    const size_t gOff1 = (size_t)(r0 + 64) * 8192 + q0 * 16;

#define LOAD_STAGE(s, kt) { \
    uint32_t sa = sm + (uint32_t)(s) * STGB; \
    const char* ga = gA + (size_t)(kt) * BKB; \
    const char* gb = gB + (size_t)(kt) * BKB; \
    cp16(sa + offL0,         ga + gOff0); \
    cp16(sa + offL1,         ga + gOff1); \
    cp16(sa + TILEB + offL0, gb + gOff0); \
    cp16(sa + TILEB + offL1, gb + gOff1); }

    // per-lane ldmatrix source coords
    const int arow = wm * 64 + (l & 15);
    const int aqh  = l >> 4;
    const int brow = wn * 32 + ((l >> 4) << 3) + (l & 7);
    const int bqh  = (l >> 3) & 1;

    float acc[4][4][4];
#pragma unroll
    for (int i = 0; i < 4; i++)
#pragma unroll
        for (int j = 0; j < 4; j++)
#pragma unroll
            for (int k = 0; k < 4; k++) acc[i][j][k] = 0.0f;

#pragma unroll
    for (int s = 0; s < STAGES - 1; s++) {
        LOAD_STAGE(s, s);
        asm volatile("cp.async.commit_group;" ::: "memory");
    }
    asm volatile("cp.async.wait_group %0;" :: "n"(STAGES - 2) : "memory");
    __syncthreads();

#pragma unroll 1
    for (int kt = 0; kt < KTILES; kt++) {
        int pf = kt + STAGES - 1;
        if (pf < KTILES) { LOAD_STAGE(pf & (STAGES - 1), pf); }
        asm volatile("cp.async.commit_group;" ::: "memory");

        const uint32_t base = sm + (uint32_t)(kt & (STAGES - 1)) * STGB;
#pragma unroll
        for (int ks = 0; ks < 2; ks++) {
            uint32_t a[4][4];
#pragma unroll
            for (int mi = 0; mi < 4; mi++) {
                uint32_t ad = base + swzoff(arow + mi * 16, ks * 2 + aqh);
                LDSM4(a[mi], ad);
            }
            uint32_t b[2][4];
#pragma unroll
            for (int nb = 0; nb < 2; nb++) {
                uint32_t ad = base + TILEB + swzoff(brow + nb * 16, ks * 2 + bqh);
                LDSM4(b[nb], ad);
            }
#pragma unroll
            for (int mi = 0; mi < 4; mi++) {
#pragma unroll
                for (int ni = 0; ni < 4; ni++) {
                    const uint32_t* bb = b[ni >> 1];
                    MMA(acc[mi][ni], a[mi], bb[2 * (ni & 1)], bb[2 * (ni & 1) + 1]);
                }
            }
        }
        asm volatile("cp.async.wait_group %0;" :: "n"(STAGES - 2) : "memory");
        __syncthreads();
    }

    // ---- epilogue: + H (fp32 identity), store ----
    const int m0 = by * BM + wm * 64;
    const int c0 = bx * BN + wn * 32;
#pragma unroll
    for (int mi = 0; mi < 4; mi++) {
#pragma unroll
        for (int ni = 0; ni < 4; ni++) {
            int m = m0 + mi * 16 + (l >> 2);
            int c = c0 + ni * 8 + 2 * (l & 3);
            float2 i0 = *reinterpret_cast<const float2*>(Hf + (size_t)m * CC + c);
            float2 i1 = *reinterpret_cast<const float2*>(Hf + (size_t)(m + 8) * CC + c);
            float2 o0 = make_float2(acc[mi][ni][0] + i0.x, acc[mi][ni][1] + i0.y);
            float2 o1 = make_float2(acc[mi][ni][2] + i1.x, acc[mi][ni][3] + i1.y);
            if (final_layer) {
                int b = c >> 4, d = c & 15;
                *reinterpret_cast<float2*>(Dout + ((size_t)b * NN + m) * DD + d) = o0;
                *reinterpret_cast<float2*>(Dout + ((size_t)b * NN + m + 8) * DD + d) = o1;
            } else {
                *reinterpret_cast<float2*>(Cout + (size_t)m * CC + c) = o0;
                *reinterpret_cast<float2*>(Cout + (size_t)(m + 8) * CC + c) = o1;
            }
        }
    }
#undef LOAD_STAGE
}

// ================= launch =================
extern "C" void kernel_launch(void* const* d_in, const int* in_sizes, int n_in,
                              void* d_out, int out_size) {
    const float* x   = (const float*)d_in[0];
    const float* adj = (const float*)d_in[1];
    const float* W0  = (const float*)d_in[3];
    const float* W1  = (const float*)d_in[4];
    const float* W2  = (const float*)d_in[5];
    float* out = (float*)d_out;

    float *pH, *pO;
    __nv_bfloat16 *pAb, *pHT;
    cudaGetSymbolAddress((void**)&pH,  g_H);
    cudaGetSymbolAddress((void**)&pO,  g_O);
    cudaGetSymbolAddress((void**)&pAb, g_adjb);
    cudaGetSymbolAddress((void**)&pHT, g_HT);

    cudaFuncSetAttribute(gemm_mma_kernel, cudaFuncAttributeMaxDynamicSharedMemorySize, DSMEM);

    const int lin_blocks = (NN * NB_B) / 256;
    dim3 tgrid(CC / 32, NN / 32), tblk(32, 8);
    dim3 ggrid(CC / BN, NN / BM);                  // (8, 32)

    cvt_adj_kernel<<<(NN * NN) / (256 * 8), 256>>>(adj, pAb);

    lin_lrelu_kernel<<<lin_blocks, 256>>>(x, W0, pH, 0);
    transpose_kernel<<<tgrid, tblk>>>(pH, pHT);
    gemm_mma_kernel<<<ggrid, 256, DSMEM>>>(pAb, pHT, pH, pO, nullptr, 0);

    lin_lrelu_kernel<<<lin_blocks, 256>>>(pO, W1, pH, 1);
    transpose_kernel<<<tgrid, tblk>>>(pH, pHT);
    gemm_mma_kernel<<<ggrid, 256, DSMEM>>>(pAb, pHT, pH, pO, nullptr, 0);

    lin_lrelu_kernel<<<lin_blocks, 256>>>(pO, W2, pH, 1);
    transpose_kernel<<<tgrid, tblk>>>(pH, pHT);
    gemm_mma_kernel<<<ggrid, 256, DSMEM>>>(pAb, pHT, pH, nullptr, out, 1);
}

// round 4
// speedup vs baseline: 7.8079x; 1.2052x over previous
#include <cuda_runtime.h>
#include <cuda_bf16.h>
#include <cstdint>

#define NB_B 64
#define NN   4096
#define DD   16
#define CC   1024

#define BM 128
#define BN 128
#define BKB 64              // K bytes per stage (32 bf16)
#define STAGES 4
#define KTILES 128          // 4096/32
#define TILEB 8192          // one operand tile: 128 rows * 64 B
#define STGB  (2*TILEB)     // 16 KB per stage
#define DSMEM (STAGES*STGB) // 64 KB

// ---- scratch ----
__device__ float          g_H [(size_t)NN*CC];
__device__ float          g_O [(size_t)NN*CC];
__device__ __nv_bfloat16  g_adjb[(size_t)NN*NN];
__device__ __nv_bfloat16  g_HT[(size_t)CC*NN];

__device__ __forceinline__ uint32_t smem_u32(const void* p) {
    uint32_t a;
    asm("{ .reg .u64 t; cvta.to.shared.u64 t, %1; cvt.u32.u64 %0, t; }" : "=r"(a) : "l"(p));
    return a;
}
__device__ __forceinline__ void cp16(uint32_t dst, const void* src) {
    asm volatile("cp.async.cg.shared.global [%0], [%1], 16;" :: "r"(dst), "l"(src) : "memory");
}
// 64B rows, 4x16B chunks; conflict-free for ldmatrix phases
__device__ __forceinline__ uint32_t swzoff(int r, int q) {
    return (uint32_t)((r << 6) + ((q ^ ((r >> 1) & 3)) << 4));
}

#define LDSM4(R, addr) \
    asm volatile("ldmatrix.sync.aligned.m8n8.x4.shared.b16 {%0,%1,%2,%3}, [%4];" \
        : "=r"((R)[0]), "=r"((R)[1]), "=r"((R)[2]), "=r"((R)[3]) : "r"(addr))

#define MMA(C, A_, B0, B1) \
    asm volatile("mma.sync.aligned.m16n8k16.row.col.f32.bf16.bf16.f32 " \
        "{%0,%1,%2,%3}, {%4,%5,%6,%7}, {%8,%9}, {%0,%1,%2,%3};" \
        : "+f"((C)[0]), "+f"((C)[1]), "+f"((C)[2]), "+f"((C)[3]) \
        : "r"((A_)[0]), "r"((A_)[1]), "r"((A_)[2]), "r"((A_)[3]), "r"(B0), "r"(B1))

// ================= adj fp32 -> bf16 =================
__global__ void cvt_adj_kernel(const float* __restrict__ A, __nv_bfloat16* __restrict__ Ab) {
    size_t idx = (size_t)blockIdx.x * 256 + threadIdx.x;
    const float4* src = reinterpret_cast<const float4*>(A) + idx * 2;
    float4 a = src[0], b = src[1];
    union { __nv_bfloat162 h[4]; uint4 u; } pk;
    pk.h[0] = __floats2bfloat162_rn(a.x, a.y);
    pk.h[1] = __floats2bfloat162_rn(a.z, a.w);
    pk.h[2] = __floats2bfloat162_rn(b.x, b.y);
    pk.h[3] = __floats2bfloat162_rn(b.z, b.w);
    reinterpret_cast<uint4*>(Ab)[idx] = pk.u;
}

// ================= h = lrelu(x@W) fp32 [m,c] =================
__global__ void lin_lrelu_kernel(const float* __restrict__ X, const float* __restrict__ W,
                                 float* __restrict__ H, int mode) {
    __shared__ float sW[DD][DD];
    int t = threadIdx.x;
    sW[t >> 4][t & 15] = W[t];
    __syncthreads();
    int idx = blockIdx.x * 256 + t;
    int m = idx >> 6, b = idx & 63;
    const float* xp = mode ? (X + (size_t)m * CC + (size_t)b * DD)
                           : (X + ((size_t)b * NN + m) * DD);
    float xv[16];
#pragma unroll
    for (int j = 0; j < 4; j++) {
        float4 v = reinterpret_cast<const float4*>(xp)[j];
        xv[4*j] = v.x; xv[4*j+1] = v.y; xv[4*j+2] = v.z; xv[4*j+3] = v.w;
    }
    float h[16];
#pragma unroll
    for (int e = 0; e < 16; e++) h[e] = 0.0f;
#pragma unroll
    for (int d = 0; d < 16; d++) {
        float xd = xv[d];
#pragma unroll
        for (int e = 0; e < 16; e++) h[e] = fmaf(xd, sW[d][e], h[e]);
    }
    float* hp = H + (size_t)m * CC + (size_t)b * DD;
#pragma unroll
    for (int j = 0; j < 4; j++) {
        float4 v;
        v.x = h[4*j]   > 0.f ? h[4*j]   : 0.2f*h[4*j];
        v.y = h[4*j+1] > 0.f ? h[4*j+1] : 0.2f*h[4*j+1];
        v.z = h[4*j+2] > 0.f ? h[4*j+2] : 0.2f*h[4*j+2];
        v.w = h[4*j+3] > 0.f ? h[4*j+3] : 0.2f*h[4*j+3];
        reinterpret_cast<float4*>(hp)[j] = v;
    }
}

// ================= H [m,c] fp32 -> H^T [c,m] bf16 =================
__global__ void transpose_kernel(const float* __restrict__ H, __nv_bfloat16* __restrict__ HT) {
    __shared__ float tile[32][33];
    int c0 = blockIdx.x * 32, m0 = blockIdx.y * 32;
    int tx = threadIdx.x, ty = threadIdx.y;
#pragma unroll
    for (int j = 0; j < 4; j++)
        tile[ty + 8*j][tx] = H[(size_t)(m0 + ty + 8*j) * CC + c0 + tx];
    __syncthreads();
#pragma unroll
    for (int j = 0; j < 4; j++)
        HT[(size_t)(c0 + ty + 8*j) * NN + m0 + tx] = __float2bfloat16(tile[tx][ty + 8*j]);
}

// ================= HMMA GEMM: out = adj@H + H =================
// 128 threads, 4 warps in 2x2 grid, warp tile 64x64, 2 CTAs/SM.
__global__ __launch_bounds__(128, 2)
void gemm_mma_kernel(const __nv_bfloat16* __restrict__ Ab,   // [4096,4096] bf16 row-major
                     const __nv_bfloat16* __restrict__ Bt,   // [1024,4096] bf16 (H^T)
                     const float* __restrict__ Hf,           // [4096,1024] fp32
                     float* __restrict__ Cout, float* __restrict__ Dout,
                     int final_layer) {
    extern __shared__ char dsm[];
    const uint32_t sm = smem_u32(dsm);
    const int tid = threadIdx.x, wid = tid >> 5, l = tid & 31;
    const int bx = blockIdx.x, by = blockIdx.y;
    const int wm = wid >> 1, wn = wid & 1;     // 2x2 warp grid -> 64x64 warp tile

    const char* gA = (const char*)(Ab + (size_t)by * BM * NN);
    const char* gB = (const char*)(Bt + (size_t)bx * BN * NN);

    // producer: each thread copies 4 A segs + 4 B segs of 16B per stage
    const int r0 = tid >> 2, q0 = tid & 3;     // r0: 0..31
    uint32_t offL[4];
    size_t gOff[4];
#pragma unroll
    for (int i = 0; i < 4; i++) {
        offL[i] = swzoff(r0 + 32 * i, q0);
        gOff[i] = (size_t)(r0 + 32 * i) * 8192 + q0 * 16;
    }

#define LOAD_STAGE(s, kt) { \
    uint32_t sa = sm + (uint32_t)(s) * STGB; \
    const char* ga = gA + (size_t)(kt) * BKB; \
    const char* gb = gB + (size_t)(kt) * BKB; \
    _Pragma("unroll") \
    for (int i_ = 0; i_ < 4; i_++) { \
        cp16(sa + offL[i_],         ga + gOff[i_]); \
        cp16(sa + TILEB + offL[i_], gb + gOff[i_]); } }

    // per-lane ldmatrix source coords
    const int arow = wm * 64 + (l & 15);
    const int aqh  = l >> 4;
    const int brow = wn * 64 + ((l >> 4) << 3) + (l & 7);
    const int bqh  = (l >> 3) & 1;

    float acc[4][8][4];
#pragma unroll
    for (int i = 0; i < 4; i++)
#pragma unroll
        for (int j = 0; j < 8; j++)
#pragma unroll
            for (int k = 0; k < 4; k++) acc[i][j][k] = 0.0f;

#pragma unroll
    for (int s = 0; s < STAGES - 1; s++) {
        LOAD_STAGE(s, s);
        asm volatile("cp.async.commit_group;" ::: "memory");
    }
    asm volatile("cp.async.wait_group %0;" :: "n"(STAGES - 2) : "memory");
    __syncthreads();

    uint32_t a[2][4][4], b[2][4][4];

#pragma unroll 1
    for (int kt = 0; kt < KTILES; kt++) {
        int pf = kt + STAGES - 1;
        if (pf < KTILES) { LOAD_STAGE(pf & (STAGES - 1), pf); }
        asm volatile("cp.async.commit_group;" ::: "memory");

        const uint32_t base = sm + (uint32_t)(kt & (STAGES - 1)) * STGB;

        // load ks=0 fragments
#pragma unroll
        for (int mi = 0; mi < 4; mi++) LDSM4(a[0][mi], base + swzoff(arow + mi * 16, aqh));
#pragma unroll
        for (int nb = 0; nb < 4; nb++) LDSM4(b[0][nb], base + TILEB + swzoff(brow + nb * 16, bqh));

#pragma unroll
        for (int ks = 0; ks < 2; ks++) {
            if (ks == 0) {  // prefetch ks=1 fragments before issuing ks=0 MMAs
#pragma unroll
                for (int mi = 0; mi < 4; mi++)
                    LDSM4(a[1][mi], base + swzoff(arow + mi * 16, 2 + aqh));
#pragma unroll
                for (int nb = 0; nb < 4; nb++)
                    LDSM4(b[1][nb], base + TILEB + swzoff(brow + nb * 16, 2 + bqh));
            }
#pragma unroll
            for (int mi = 0; mi < 4; mi++) {
#pragma unroll
                for (int ni = 0; ni < 8; ni++) {
                    const uint32_t* bb = b[ks][ni >> 1];
                    MMA(acc[mi][ni], a[ks][mi], bb[2 * (ni & 1)], bb[2 * (ni & 1) + 1]);
                }
            }
        }
        asm volatile("cp.async.wait_group %0;" :: "n"(STAGES - 2) : "memory");
        __syncthreads();
    }

    // ---- epilogue: + H (fp32 identity), store ----
    const int m0 = by * BM + wm * 64;
    const int c0 = bx * BN + wn * 64;
#pragma unroll
    for (int mi = 0; mi < 4; mi++) {
#pragma unroll
        for (int ni = 0; ni < 8; ni++) {
            int m = m0 + mi * 16 + (l >> 2);
            int c = c0 + ni * 8 + 2 * (l & 3);
            float2 i0 = *reinterpret_cast<const float2*>(Hf + (size_t)m * CC + c);
            float2 i1 = *reinterpret_cast<const float2*>(Hf + (size_t)(m + 8) * CC + c);
            float2 o0 = make_float2(acc[mi][ni][0] + i0.x, acc[mi][ni][1] + i0.y);
            float2 o1 = make_float2(acc[mi][ni][2] + i1.x, acc[mi][ni][3] + i1.y);
            if (final_layer) {
                int bq = c >> 4, d = c & 15;
                *reinterpret_cast<float2*>(Dout + ((size_t)bq * NN + m) * DD + d) = o0;
                *reinterpret_cast<float2*>(Dout + ((size_t)bq * NN + m + 8) * DD + d) = o1;
            } else {
                *reinterpret_cast<float2*>(Cout + (size_t)m * CC + c) = o0;
                *reinterpret_cast<float2*>(Cout + (size_t)(m + 8) * CC + c) = o1;
            }
        }
    }
#undef LOAD_STAGE
}

// ================= launch =================
extern "C" void kernel_launch(void* const* d_in, const int* in_sizes, int n_in,
                              void* d_out, int out_size) {
    const float* x   = (const float*)d_in[0];
    const float* adj = (const float*)d_in[1];
    const float* W0  = (const float*)d_in[3];
    const float* W1  = (const float*)d_in[4];
    const float* W2  = (const float*)d_in[5];
    float* out = (float*)d_out;

    float *pH, *pO;
    __nv_bfloat16 *pAb, *pHT;
    cudaGetSymbolAddress((void**)&pH,  g_H);
    cudaGetSymbolAddress((void**)&pO,  g_O);
    cudaGetSymbolAddress((void**)&pAb, g_adjb);
    cudaGetSymbolAddress((void**)&pHT, g_HT);

    cudaFuncSetAttribute(gemm_mma_kernel, cudaFuncAttributeMaxDynamicSharedMemorySize, DSMEM);

    const int lin_blocks = (NN * NB_B) / 256;
    dim3 tgrid(CC / 32, NN / 32), tblk(32, 8);
    dim3 ggrid(CC / BN, NN / BM);                  // (8, 32)

    cvt_adj_kernel<<<(NN * NN) / (256 * 8), 256>>>(adj, pAb);

    lin_lrelu_kernel<<<lin_blocks, 256>>>(x, W0, pH, 0);
    transpose_kernel<<<tgrid, tblk>>>(pH, pHT);
    gemm_mma_kernel<<<ggrid, 128, DSMEM>>>(pAb, pHT, pH, pO, nullptr, 0);

    lin_lrelu_kernel<<<lin_blocks, 256>>>(pO, W1, pH, 1);
    transpose_kernel<<<tgrid, tblk>>>(pH, pHT);
    gemm_mma_kernel<<<ggrid, 128, DSMEM>>>(pAb, pHT, pH, pO, nullptr, 0);

    lin_lrelu_kernel<<<lin_blocks, 256>>>(pO, W2, pH, 1);
    transpose_kernel<<<tgrid, tblk>>>(pH, pHT);
    gemm_mma_kernel<<<ggrid, 128, DSMEM>>>(pAb, pHT, pH, nullptr, out, 1);
}

// round 5
// speedup vs baseline: 7.8087x; 1.0001x over previous
#include <cuda_runtime.h>
#include <cuda_bf16.h>
#include <cstdint>

#define NB_B 64
#define NN   4096
#define DD   16
#define CC   1024

#define BM 128
#define BN 128
#define BKB 128             // K bytes per stage (64 bf16)
#define STAGES 3
#define KTILES 64           // 4096/64
#define TILEB (128*128)     // one operand tile: 128 rows * 128 B = 16 KB
#define STGB  (2*TILEB)     // 32 KB per stage
#define DSMEM (STAGES*STGB) // 96 KB

// ---- scratch ----
__device__ float          g_H [(size_t)NN*CC];
__device__ float          g_O [(size_t)NN*CC];
__device__ __nv_bfloat16  g_adjb[(size_t)NN*NN];
__device__ __nv_bfloat16  g_HT[(size_t)CC*NN];

__device__ __forceinline__ uint32_t smem_u32(const void* p) {
    uint32_t a;
    asm("{ .reg .u64 t; cvta.to.shared.u64 t, %1; cvt.u32.u64 %0, t; }" : "=r"(a) : "l"(p));
    return a;
}
__device__ __forceinline__ void cp16(uint32_t dst, const void* src) {
    asm volatile("cp.async.cg.shared.global [%0], [%1], 16;" :: "r"(dst), "l"(src) : "memory");
}
// 128B rows, 8x16B chunks, SW128: chunk q XOR low 3 row bits
__device__ __forceinline__ uint32_t swz(int r, int q) {
    return (uint32_t)((r << 7) + ((q ^ (r & 7)) << 4));
}

#define LDSM4(R, addr) \
    asm volatile("ldmatrix.sync.aligned.m8n8.x4.shared.b16 {%0,%1,%2,%3}, [%4];" \
        : "=r"((R)[0]), "=r"((R)[1]), "=r"((R)[2]), "=r"((R)[3]) : "r"(addr))

#define MMA(C, A_, B0, B1) \
    asm volatile("mma.sync.aligned.m16n8k16.row.col.f32.bf16.bf16.f32 " \
        "{%0,%1,%2,%3}, {%4,%5,%6,%7}, {%8,%9}, {%0,%1,%2,%3};" \
        : "+f"((C)[0]), "+f"((C)[1]), "+f"((C)[2]), "+f"((C)[3]) \
        : "r"((A_)[0]), "r"((A_)[1]), "r"((A_)[2]), "r"((A_)[3]), "r"(B0), "r"(B1))

// ================= adj fp32 -> bf16 =================
__global__ void cvt_adj_kernel(const float* __restrict__ A, __nv_bfloat16* __restrict__ Ab) {
    size_t idx = (size_t)blockIdx.x * 256 + threadIdx.x;
    const float4* src = reinterpret_cast<const float4*>(A) + idx * 2;
    float4 a = src[0], b = src[1];
    union { __nv_bfloat162 h[4]; uint4 u; } pk;
    pk.h[0] = __floats2bfloat162_rn(a.x, a.y);
    pk.h[1] = __floats2bfloat162_rn(a.z, a.w);
    pk.h[2] = __floats2bfloat162_rn(b.x, b.y);
    pk.h[3] = __floats2bfloat162_rn(b.z, b.w);
    reinterpret_cast<uint4*>(Ab)[idx] = pk.u;
}

// ===== fused: h = lrelu(X@W); write H fp32 [m,c] AND HT bf16 [c,m] =====
// tile: 32 m-rows x 32 c-cols (= 2 batches). grid (CC/32, NN/32), 256 thr.
__global__ __launch_bounds__(256)
void lin_tr_kernel(const float* __restrict__ X, const float* __restrict__ W,
                   float* __restrict__ H, __nv_bfloat16* __restrict__ HT, int mode) {
    __shared__ float sW[DD][DD];
    __shared__ float sX[2][32][DD];          // [b-loc][m][d]
    __shared__ __nv_bfloat16 sT[32][33];     // [c-loc][m]

    const int t = threadIdx.x;
    const int c0 = blockIdx.x * 32, m0 = blockIdx.y * 32, b0 = c0 >> 4;

    sW[t >> 4][t & 15] = W[t];

    // load X tile: 2 b x 32 m x 16 d, float4 per thread
    {
        int bloc = t >> 7, m = (t >> 2) & 31, seg = t & 3;
        const float* xp = mode
            ? (X + (size_t)(m0 + m) * CC + (size_t)(b0 + bloc) * DD + seg * 4)
            : (X + ((size_t)(b0 + bloc) * NN + (m0 + m)) * DD + seg * 4);
        float4 v = *reinterpret_cast<const float4*>(xp);
        sX[bloc][m][seg*4]   = v.x; sX[bloc][m][seg*4+1] = v.y;
        sX[bloc][m][seg*4+2] = v.z; sX[bloc][m][seg*4+3] = v.w;
    }
    __syncthreads();

    // compute: thread -> (m, quad); 4 consecutive c values
    {
        int m = t >> 3, quad = t & 7;
        int bloc = quad >> 2;
        int e0 = (quad & 3) * 4;
        float h[4] = {0.f, 0.f, 0.f, 0.f};
#pragma unroll
        for (int d = 0; d < DD; d++) {
            float xd = sX[bloc][m][d];
#pragma unroll
            for (int j = 0; j < 4; j++) h[j] = fmaf(xd, sW[d][e0 + j], h[j]);
        }
#pragma unroll
        for (int j = 0; j < 4; j++) h[j] = h[j] > 0.f ? h[j] : 0.2f * h[j];

        float4 v = make_float4(h[0], h[1], h[2], h[3]);
        *reinterpret_cast<float4*>(H + (size_t)(m0 + m) * CC + c0 + quad * 4) = v;
#pragma unroll
        for (int j = 0; j < 4; j++) sT[quad * 4 + j][m] = __float2bfloat16(h[j]);
    }
    __syncthreads();

    // write HT: thread -> (c, seg of 4 m)
    {
        int c = t >> 3, seg = t & 7;
        union { __nv_bfloat16 h[4]; uint2 u; } pk;
#pragma unroll
        for (int j = 0; j < 4; j++) pk.h[j] = sT[c][seg * 4 + j];
        *reinterpret_cast<uint2*>(HT + (size_t)(c0 + c) * NN + m0 + seg * 4) = pk.u;
    }
}

// ================= HMMA GEMM: out = adj@H + H =================
// 128 threads, 4 warps 2x2, warp tile 64x64, BK=64, 3 stages, 2 CTAs/SM.
__global__ __launch_bounds__(128, 2)
void gemm_mma_kernel(const __nv_bfloat16* __restrict__ Ab,   // [4096,4096] bf16
                     const __nv_bfloat16* __restrict__ Bt,   // [1024,4096] bf16 (H^T)
                     const float* __restrict__ Hf,           // [4096,1024] fp32
                     float* __restrict__ Cout, float* __restrict__ Dout,
                     int final_layer) {
    extern __shared__ char dsm[];
    const uint32_t sm = smem_u32(dsm);
    const int tid = threadIdx.x, wid = tid >> 5, l = tid & 31;
    const int bx = blockIdx.x, by = blockIdx.y;
    const int wm = wid >> 1, wn = wid & 1;

    const char* gA = (const char*)(Ab + (size_t)by * BM * NN);
    const char* gB = (const char*)(Bt + (size_t)bx * BN * NN);

    // producer: 16 cp16/thread/stage (8 A + 8 B)
    const int r0 = tid >> 3, q0 = tid & 7;     // r0: 0..15
    uint32_t offL[8];
    size_t gOff[8];
#pragma unroll
    for (int i = 0; i < 8; i++) {
        offL[i] = swz(r0 + 16 * i, q0);
        gOff[i] = (size_t)(r0 + 16 * i) * 8192 + q0 * 16;
    }

#define LOAD_STAGE(s, kt) { \
    uint32_t sa = sm + (uint32_t)(s) * STGB; \
    const char* ga = gA + (size_t)(kt) * BKB; \
    const char* gb = gB + (size_t)(kt) * BKB; \
    _Pragma("unroll") \
    for (int i_ = 0; i_ < 8; i_++) { \
        cp16(sa + offL[i_],         ga + gOff[i_]); \
        cp16(sa + TILEB + offL[i_], gb + gOff[i_]); } }

    const int arow = wm * 64 + (l & 15);
    const int aqh  = l >> 4;
    const int brow = wn * 64 + ((l >> 4) << 3) + (l & 7);
    const int bqh  = (l >> 3) & 1;

    float acc[4][8][4];
#pragma unroll
    for (int i = 0; i < 4; i++)
#pragma unroll
        for (int j = 0; j < 8; j++)
#pragma unroll
            for (int k = 0; k < 4; k++) acc[i][j][k] = 0.0f;

#pragma unroll
    for (int s = 0; s < STAGES - 1; s++) {
        LOAD_STAGE(s, s);
        asm volatile("cp.async.commit_group;" ::: "memory");
    }
    asm volatile("cp.async.wait_group %0;" :: "n"(STAGES - 2) : "memory");
    __syncthreads();

    uint32_t a[2][4][4], b[2][4][4];
    int pidx = STAGES - 1;   // stage slot for prefetch
    int cidx = 0;            // stage slot being consumed

#pragma unroll 1
    for (int kt = 0; kt < KTILES; kt++) {
        int pf = kt + STAGES - 1;
        if (pf < KTILES) { LOAD_STAGE(pidx, pf); }
        asm volatile("cp.async.commit_group;" ::: "memory");
        if (++pidx == STAGES) pidx = 0;

        const uint32_t base = sm + (uint32_t)cidx * STGB;
        if (++cidx == STAGES) cidx = 0;

        // ks=0 fragments
#pragma unroll
        for (int mi = 0; mi < 4; mi++) LDSM4(a[0][mi], base + swz(arow + mi * 16, aqh));
#pragma unroll
        for (int nb = 0; nb < 4; nb++) LDSM4(b[0][nb], base + TILEB + swz(brow + nb * 16, bqh));

#pragma unroll
        for (int ks = 0; ks < 4; ks++) {
            int cur = ks & 1, nxt = cur ^ 1;
            if (ks < 3) {   // prefetch ks+1 fragments
#pragma unroll
                for (int mi = 0; mi < 4; mi++)
                    LDSM4(a[nxt][mi], base + swz(arow + mi * 16, (ks + 1) * 2 + aqh));
#pragma unroll
                for (int nb = 0; nb < 4; nb++)
                    LDSM4(b[nxt][nb], base + TILEB + swz(brow + nb * 16, (ks + 1) * 2 + bqh));
            }
#pragma unroll
            for (int mi = 0; mi < 4; mi++) {
#pragma unroll
                for (int ni = 0; ni < 8; ni++) {
                    const uint32_t* bb = b[cur][ni >> 1];
                    MMA(acc[mi][ni], a[cur][mi], bb[2 * (ni & 1)], bb[2 * (ni & 1) + 1]);
                }
            }
        }
        asm volatile("cp.async.wait_group %0;" :: "n"(STAGES - 2) : "memory");
        __syncthreads();
    }

    // ---- epilogue: + H (fp32 identity), store ----
    const int m0 = by * BM + wm * 64;
    const int c0 = bx * BN + wn * 64;
#pragma unroll
    for (int mi = 0; mi < 4; mi++) {
#pragma unroll
        for (int ni = 0; ni < 8; ni++) {
            int m = m0 + mi * 16 + (l >> 2);
            int c = c0 + ni * 8 + 2 * (l & 3);
            float2 i0 = *reinterpret_cast<const float2*>(Hf + (size_t)m * CC + c);
            float2 i1 = *reinterpret_cast<const float2*>(Hf + (size_t)(m + 8) * CC + c);
            float2 o0 = make_float2(acc[mi][ni][0] + i0.x, acc[mi][ni][1] + i0.y);
            float2 o1 = make_float2(acc[mi][ni][2] + i1.x, acc[mi][ni][3] + i1.y);
            if (final_layer) {
                int bq = c >> 4, d = c & 15;
                *reinterpret_cast<float2*>(Dout + ((size_t)bq * NN + m) * DD + d) = o0;
                *reinterpret_cast<float2*>(Dout + ((size_t)bq * NN + m + 8) * DD + d) = o1;
            } else {
                *reinterpret_cast<float2*>(Cout + (size_t)m * CC + c) = o0;
                *reinterpret_cast<float2*>(Cout + (size_t)(m + 8) * CC + c) = o1;
            }
        }
    }
#undef LOAD_STAGE
}

// ================= launch =================
extern "C" void kernel_launch(void* const* d_in, const int* in_sizes, int n_in,
                              void* d_out, int out_size) {
    const float* x   = (const float*)d_in[0];
    const float* adj = (const float*)d_in[1];
    const float* W0  = (const float*)d_in[3];
    const float* W1  = (const float*)d_in[4];
    const float* W2  = (const float*)d_in[5];
    float* out = (float*)d_out;

    float *pH, *pO;
    __nv_bfloat16 *pAb, *pHT;
    cudaGetSymbolAddress((void**)&pH,  g_H);
    cudaGetSymbolAddress((void**)&pO,  g_O);
    cudaGetSymbolAddress((void**)&pAb, g_adjb);
    cudaGetSymbolAddress((void**)&pHT, g_HT);

    cudaFuncSetAttribute(gemm_mma_kernel, cudaFuncAttributeMaxDynamicSharedMemorySize, DSMEM);

    dim3 lgrid(CC / 32, NN / 32);                  // (32, 128)
    dim3 ggrid(CC / BN, NN / BM);                  // (8, 32)

    cvt_adj_kernel<<<(NN * NN) / (256 * 8), 256>>>(adj, pAb);

    lin_tr_kernel<<<lgrid, 256>>>(x, W0, pH, pHT, 0);
    gemm_mma_kernel<<<ggrid, 128, DSMEM>>>(pAb, pHT, pH, pO, nullptr, 0);

    lin_tr_kernel<<<lgrid, 256>>>(pO, W1, pH, pHT, 1);
    gemm_mma_kernel<<<ggrid, 128, DSMEM>>>(pAb, pHT, pH, pO, nullptr, 0);

    lin_tr_kernel<<<lgrid, 256>>>(pO, W2, pH, pHT, 1);
    gemm_mma_kernel<<<ggrid, 128, DSMEM>>>(pAb, pHT, pH, nullptr, out, 1);
}